// round 10
// baseline (speedup 1.0000x reference)
#include <cuda_runtime.h>
#include <cuda_bf16.h>

// Problem constants (fixed shapes from reference setup_inputs)
#define BB 4
#define NN 16384
#define PP 1024
#define CC 128
#define NS 64
#define R2 0.04f

#define NQBLK (BB * PP / 4)   // 1024 query blocks (scheduled FIRST, R6 finding)
#define NTBLK (BB * 512 * 4)  // 8192 transpose blocks

// Scratch (allocations forbidden; __device__ globals)
__device__ float g_ftrans[(size_t)BB * NN * CC];   // (B, N, C), 32 MB
__device__ int   g_idx[BB * PP * NS];              // masked gather indices

// Swizzled tile address: 64 s-rows x 64 channels, 16B-group XOR swizzle.
__device__ __forceinline__ int taddr(int s, int ch) {
    return s * 64 + (((ch >> 2) ^ (s & 15)) << 2) + (ch & 3);
}

// ---------------------------------------------------------------------------
// Mega-chunk ball query for 4 centers per block.
// Per 4096-pt chunk: warps evaluate disjoint 512-pt slices independently
// (masks -> smem, packed counts -> smem), ONE barrier, u64-SIMD cross-warp
// prefix, then an ordered mask re-walk scatters hits. Index order is
// preserved structurally (warp w owns indices [w*512,(w+1)*512) of the chunk).
// ---------------------------------------------------------------------------
__device__ __forceinline__ void ball_query_4(
    const int pb0, const float* __restrict__ xyz,
    const float* __restrict__ new_xyz, float* __restrict__ out) {
    __shared__ unsigned msk[2][4][8][16];          // [buf][center][warp][round]
    __shared__ unsigned long long wct[2][8];       // packed counts, 16b fields
    __shared__ int sidx[4][NS];
    const int t = threadIdx.x;
    const int warp = t >> 5;
    const int lane = t & 31;
    const int b = pb0 >> 10;
    const float* xb = xyz + (size_t)b * NN * 3;
    const unsigned lm = (1u << lane) - 1u;

    float qx[4], qy[4], qz[4];
#pragma unroll
    for (int g = 0; g < 4; g++) {
        qx[g] = new_xyz[(size_t)(pb0 + g) * 3 + 0];
        qy[g] = new_xyz[(size_t)(pb0 + g) * 3 + 1];
        qz[g] = new_xyz[(size_t)(pb0 + g) * 3 + 2];
    }

    int cnt[4] = {0, 0, 0, 0};
    int sel = 0;
    for (int m = 0; m < NN / 4096; m++) {
        const int pbase = m * 4096 + warp * 512;
        unsigned long long c4 = 0;
        // ---- Phase A: evaluate own 512-pt slice, no coordination ----
#pragma unroll
        for (int rg = 0; rg < 4; rg++) {
            float xs[4], ys[4], zs[4];
#pragma unroll
            for (int r = 0; r < 4; r++) {          // prefetch 4 rounds
                const int i = pbase + (rg * 4 + r) * 32 + lane;
                xs[r] = xb[i * 3 + 0];
                ys[r] = xb[i * 3 + 1];
                zs[r] = xb[i * 3 + 2];
            }
#pragma unroll
            for (int r = 0; r < 4; r++) {
#pragma unroll
                for (int g = 0; g < 4; g++) {
                    if (cnt[g] < NS) {             // uniform across block
                        // JAX f32 rounding: no FMA, left-to-right sum.
                        const float dx = __fadd_rn(qx[g], -xs[r]);
                        const float dy = __fadd_rn(qy[g], -ys[r]);
                        const float dz = __fadd_rn(qz[g], -zs[r]);
                        const float d2 = __fadd_rn(
                            __fadd_rn(__fmul_rn(dx, dx), __fmul_rn(dy, dy)),
                            __fmul_rn(dz, dz));
                        const unsigned mk =
                            __ballot_sync(0xffffffffu, d2 < R2);
                        if (lane == 0) msk[sel][g][warp][rg * 4 + r] = mk;
                        c4 += (unsigned long long)__popc(mk) << (16 * g);
                    }
                }
            }
        }
        if (lane == 0) wct[sel][warp] = c4;
        __syncthreads();   // the ONLY barrier per mega-chunk (double-buffered)

        // ---- Phase B: cross-warp prefix + ordered scatter ----
        unsigned long long pre = 0, tot = 0;
#pragma unroll
        for (int w = 0; w < 8; w++) {
            const unsigned long long v = wct[sel][w];
            if (w < warp) pre += v;
            tot += v;
        }
#pragma unroll
        for (int g = 0; g < 4; g++) {
            if (cnt[g] >= NS) continue;            // uniform
            int rb = cnt[g] + (int)((pre >> (16 * g)) & 0xffff);
            if (rb < NS) {
#pragma unroll 4
                for (int r = 0; r < 16; r++) {
                    const unsigned mk = msk[sel][g][warp][r];
                    if ((mk >> lane) & 1u) {
                        const int pos = rb + __popc(mk & lm);
                        if (pos < NS) sidx[g][pos] = pbase + r * 32 + lane;
                    }
                    rb += __popc(mk);
                    if (rb >= NS) break;           // uniform per warp
                }
            }
        }
#pragma unroll
        for (int g = 0; g < 4; g++)
            cnt[g] += (int)((tot >> (16 * g)) & 0xffff);
        sel ^= 1;
        if (cnt[0] >= NS && cnt[1] >= NS && cnt[2] >= NS && cnt[3] >= NS)
            break;
    }
    __syncthreads();       // sidx visible to all warps

    // ---- outputs: thread t handles center g = t>>6, slot s = t&63 ----
    {
        const int g = t >> 6;
        const int s = t & 63;
        const int p = (pb0 & 1023) + g;
        const int cn = cnt[g] < NS ? cnt[g] : NS;
        const int first = (cn > 0) ? sidx[g][0] : NN;
        const bool real = (s < cn);
        const int v = real ? sidx[g][s] : NN;
        const size_t o = (size_t)(pb0 + g) * NS;
        g_idx[o + s] = v;   // masked (pad -> NN)
        float* out_idx =
            out + (size_t)BB * 131 * PP * NS + (size_t)BB * 3 * PP * NS;
        out_idx[o + s] = (float)(real ? v : first);   // idx0 (pad -> first)

        // grouped_xyz + xyz_feature channels
        const float qgx = (g == 0) ? qx[0] : (g == 1) ? qx[1]
                          : (g == 2) ? qx[2] : qx[3];
        const float qgy = (g == 0) ? qy[0] : (g == 1) ? qy[1]
                          : (g == 2) ? qy[2] : qy[3];
        const float qgz = (g == 0) ? qz[0] : (g == 1) ? qz[1]
                          : (g == 2) ? qz[2] : qz[3];
        float* gx = out + (size_t)BB * 131 * PP * NS;
#pragma unroll
        for (int c = 0; c < 3; c++) {
            const float q = (c == 0) ? qgx : (c == 1) ? qgy : qgz;
            const float src = (v < NN) ? xb[v * 3 + c] : 1000000.0f;
            const float gv = __fadd_rn(src, -q);
            gx[(((size_t)b * 3 + c) * PP + p) * NS + s] = gv;
            const float xf = (gv > 100000.0f) ? 0.0f : gv;
            out[(((size_t)b * 131 + c) * PP + p) * NS + s] = xf / 0.2f;
        }
    }
}

// ---------------------------------------------------------------------------
// Kernel 1 (union grid): blocks [0, NQBLK) = ball query (first, backfilled by
// transpose per R6 finding); blocks [NQBLK, NQBLK+NTBLK) = transpose.
// ---------------------------------------------------------------------------
__global__ void __launch_bounds__(256) prep_kernel(
    const float* __restrict__ f, const float* __restrict__ xyz,
    const float* __restrict__ new_xyz, float* __restrict__ out) {
    const int bi = blockIdx.x;
    if (bi < NQBLK) {
        ball_query_4(bi * 4, xyz, new_xyz, out);
    } else {
        // ---------------- transpose (B,C,N) -> (B,N,C) ----------------
        __shared__ float tile[32][33];
        const int t = threadIdx.x;
        const int tb = bi - NQBLK;        // 0..8191
        const int b = tb >> 11;           // 2048 blocks per batch
        const int rem = tb & 2047;
        const int nBase = (rem >> 2) * 32;
        const int cBase = (rem & 3) * 32;
        const float* fb = f + (size_t)b * CC * NN;
        float* ob = g_ftrans + (size_t)b * NN * CC;
        const int tx = t & 31, ty = t >> 5;  // 32 x 8
#pragma unroll
        for (int i = 0; i < 32; i += 8)
            tile[ty + i][tx] = fb[(size_t)(cBase + ty + i) * NN + nBase + tx];
        __syncthreads();
#pragma unroll
        for (int i = 0; i < 32; i += 8)
            ob[(size_t)(nBase + ty + i) * CC + cBase + tx] = tile[tx][ty + i];
    }
}

// ---------------------------------------------------------------------------
// Kernel 2: feature gather. Block per (chunk-of-64-channels, p, b).
// LDG.128 gather -> STS.128 swizzled [s][ch] tile -> LDS + STG.128 output.
// ---------------------------------------------------------------------------
__global__ void __launch_bounds__(256, 8) gather_kernel(float* __restrict__ out) {
    __shared__ float ftile[64 * 64];    // 16 KB, swizzled
    __shared__ int smidx[NS];

    const int chunk = blockIdx.x;       // 0 / 1
    const int p = blockIdx.y;
    const int b = blockIdx.z;
    const int t = threadIdx.x;
    const int warp = t >> 5;
    const int lane = t & 31;

    if (t < NS) smidx[t] = g_idx[((size_t)b * PP + p) * NS + t];
    __syncthreads();

    // Phase A: gather. Warp handles 2 s-rows per iter (16 lanes x float4 each).
    const float* fb = g_ftrans + (size_t)b * NN * CC + chunk * 64;
    const int c4 = lane & 15;           // 16B group within the row
#pragma unroll
    for (int i = 0; i < 4; i++) {
        const int row = warp * 8 + i * 2 + (lane >> 4);
        const int n = smidx[row];
        float4 v = make_float4(0.f, 0.f, 0.f, 0.f);
        if (n < NN) v = *(const float4*)&fb[(size_t)n * CC + c4 * 4];
        *(float4*)&ftile[row * 64 + ((c4 ^ (row & 15)) << 2)] = v;
    }
    __syncthreads();

    // Phase B: write 64 channels x 64 s, STG.128 along s.
    float* nfb = out + (((size_t)b * 131 + 3 + chunk * 64) * PP + p) * NS;
    const int ch = t >> 2;              // 0..63 (within chunk)
#pragma unroll
    for (int k = 0; k < 4; k++) {
        const int sg = (t & 3) + 4 * k; // 0..15 (group of 4 s)
        float4 v;
        v.x = ftile[taddr(4 * sg + 0, ch)];
        v.y = ftile[taddr(4 * sg + 1, ch)];
        v.z = ftile[taddr(4 * sg + 2, ch)];
        v.w = ftile[taddr(4 * sg + 3, ch)];
        *(float4*)&nfb[(size_t)ch * PP * NS + sg * 4] = v;
    }
}

// ---------------------------------------------------------------------------
extern "C" void kernel_launch(void* const* d_in, const int* in_sizes, int n_in,
                              void* d_out, int out_size) {
    const float* xyz      = (const float*)d_in[0];  // (B, N, 3)
    const float* new_xyz  = (const float*)d_in[1];  // (B, P, 3)
    const float* features = (const float*)d_in[2];  // (B, C, N)
    float* out = (float*)d_out;

    prep_kernel<<<NQBLK + NTBLK, 256>>>(features, xyz, new_xyz, out);
    gather_kernel<<<dim3(2, PP, BB), 256>>>(out);
}